// round 12
// baseline (speedup 1.0000x reference)
#include <cuda_runtime.h>
#include <cuda_bf16.h>

// Soft local histogram, R=5, bandwidth=0.5.
// Input/output: (4, 8, 3, 256, 256) fp32 -> 96 images of 256x256.
// out[y,x] = sum_{di,dj in [-2,2]} max(0, 1 - 2*|x[y+di,x+dj] - x[y,x]|)
// for y,x in [2, 254); zero on the 2-pixel border.
//
// Tap math: d = 2(a-c); w = __saturatef(fma(|d|,-1,1)); acc = fma(w,2,acc).
// Pairwise symmetry: w(a,c) == w(c,a); the 24 neighbor pairs fully inside a
// thread's 4x2 output block are computed once (4 instrs / 2 taps). External
// taps (144) stay 3 FFMA-imm each. Owned rows (ry=2,3) only need edge cols.
// R11 showed this spills in the 32-reg bin (L2 15->26%); this round runs it
// at 6 CTAs/SM (40-reg bin) where the live set fits. Wave-tail cost of 6 vs
// 7 CTAs measured at only ~0.4% (R8 vs R10), so despilling dominates.

#define IMG_H 256
#define IMG_W 256
#define TX 8            // threads in x; each covers PX=4 pixels -> 32 wide
#define TYB 32
#define PX 4
#define PY 2
#define BW 32           // block tile width in pixels
#define BH (TYB * PY)   // 64 output rows per block
#define TILE_H (BH + 4) // 68
#define TILE_W 56       // cols: [0..3] pad, [4..51] loaded, [52..55] pad
#define NF4 12          // float4s loaded per row (48 floats, s in [4,52))
#define NLOAD (TILE_H * NF4)   // 816

__global__ __launch_bounds__(TX * TYB, 6) void soft_hist_kernel(
    const float* __restrict__ in, float* __restrict__ out)
{
    __shared__ float tile[TILE_H][TILE_W];

    const int img = blockIdx.z;
    const float* im = in + (size_t)img * IMG_H * IMG_W;
    float* om = out + (size_t)img * IMG_H * IMG_W;

    const int x0 = blockIdx.x * BW;
    const int y0 = blockIdx.y * BH;
    const int tx = threadIdx.x;
    const int ty = threadIdx.y;
    const int tid = ty * TX + tx;

    // 48-float aligned load window starting at base_x; smem col s = g - base_x + 4.
    // Edge clamps shift the window; pad/garbage cols only ever feed taps whose
    // outputs are in the forced-zero border.
    int base_x = x0 - 8;
    if (base_x < 0) base_x = 0;
    if (base_x > IMG_W - 48) base_x = IMG_W - 48;   // 208

    for (int idx = tid; idx < NLOAD; idx += TX * TYB) {
        int ly = idx / NF4;
        int lf = idx - ly * NF4;
        int gy = min(max(y0 + ly - 2, 0), IMG_H - 1);   // clamped rows feed zeros
        float4 v = *reinterpret_cast<const float4*>(im + gy * IMG_W + base_x + lf * 4);
        *reinterpret_cast<float4*>(&tile[ly][4 + lf * 4]) = v;
    }
    __syncthreads();

    // Thread outputs: cols x0 + 4*tx + p (p=0..3), rows y0 + ty*PY + k (k=0..1).
    // Cell (k,p): center at tile[rbase+k+2][scol0+p]; tap rows rbase+k..+k+4.
    const int scol0 = (x0 + PX * tx) - base_x + 4;   // smem col of output p=0
    const int rbase = ty * PY;
    const float one = 1.0f;

    // Centers: rows rbase+2..rbase+3, cols scol0..scol0+3 -> one LDS.128 each.
    float nc2[PY * PX];   // -2 * center value per cell
    float acc[PY * PX];   // 2 * running sum; center tap (w==1) pre-seeded
    #pragma unroll
    for (int k = 0; k < PY; k++) {
        float4 c = *reinterpret_cast<const float4*>(&tile[rbase + k + 2][scol0]);
        nc2[k * PX + 0] = -2.0f * c.x;
        nc2[k * PX + 1] = -2.0f * c.y;
        nc2[k * PX + 2] = -2.0f * c.z;
        nc2[k * PX + 3] = -2.0f * c.w;
        acc[k * PX + 0] = 2.0f;
        acc[k * PX + 1] = 2.0f;
        acc[k * PX + 2] = 2.0f;
        acc[k * PX + 3] = 2.0f;
    }

    // ---- Phase 1: internal pairs (both endpoints owned). Pure register math.
    // d = nc2[v] - nc2[u] = 2(val[u]-val[v]); |d| symmetric; w added to BOTH.
    #pragma unroll
    for (int k = 0; k < PY; k++) {           // same-row pairs, dp = 1, 2
        #pragma unroll
        for (int dp = 1; dp <= 2; dp++) {
            #pragma unroll
            for (int p = 0; p + dp < PX; p++) {
                int u = k * PX + p, v = k * PX + p + dp;
                float d = nc2[v] - nc2[u];
                float w = __saturatef(fmaf(fabsf(d), -1.0f, one));
                acc[u] = fmaf(w, 2.0f, acc[u]);
                acc[v] = fmaf(w, 2.0f, acc[v]);
            }
        }
    }
    #pragma unroll
    for (int p1 = 0; p1 < PX; p1++) {        // cross-row pairs, |dp| <= 2
        #pragma unroll
        for (int p2 = 0; p2 < PX; p2++) {
            if (p2 - p1 <= 2 && p1 - p2 <= 2) {
                int u = p1, v = PX + p2;     // (k=0,p1) - (k=1,p2)
                float d = nc2[v] - nc2[u];
                float w = __saturatef(fmaf(fabsf(d), -1.0f, one));
                acc[u] = fmaf(w, 2.0f, acc[u]);
                acc[v] = fmaf(w, 2.0f, acc[v]);
            }
        }
    }

    // ---- Phase 2: external taps. Tap (cell k,p; row ry; j): col a-idx i=p+j.
    // Internal (skipped) iff tap position is an owned cell: ry in {2,3} and
    // i in [2,5] (covers the center tap too). Owned rows need only edge cols.
    #pragma unroll
    for (int ry = 0; ry < PY + 4; ry++) {
        const bool ownedRow = (ry == 2 || ry == 3);
        float a[8];   // a[i] = value at global col gxb - 2 + i
        {
            const float* row = &tile[rbase + ry][0];
            float2 lo = *reinterpret_cast<const float2*>(row + scol0 - 2);
            float2 hi = *reinterpret_cast<const float2*>(row + scol0 + 4);
            a[0] = lo.x; a[1] = lo.y; a[6] = hi.x; a[7] = hi.y;
            if (!ownedRow) {
                float4 md = *reinterpret_cast<const float4*>(row + scol0);
                a[2] = md.x; a[3] = md.y; a[4] = md.z; a[5] = md.w;
            } else {
                a[2] = a[3] = a[4] = a[5] = 0.0f;   // never read (DCE'd)
            }
        }
        #pragma unroll
        for (int k = 0; k < PY; k++) {
            if (ry >= k && ry <= k + 4) {
                #pragma unroll
                for (int p = 0; p < PX; p++) {
                    #pragma unroll
                    for (int j = 0; j < 5; j++) {
                        const int i = p + j;
                        if (ownedRow && i >= 2 && i <= 5) continue;  // internal/center
                        float d = fmaf(a[i], 2.0f, nc2[k * PX + p]);       // FFMA-imm
                        float w = __saturatef(fmaf(fabsf(d), -1.0f, one)); // FFMA.SAT
                        acc[k * PX + p] = fmaf(w, 2.0f, acc[k * PX + p]);  // FFMA-imm
                    }
                }
            }
        }
    }

    // Epilogue: border select + 0.5x scale, one STG.128 per output row.
    const int gxb = x0 + PX * tx;
    #pragma unroll
    for (int k = 0; k < PY; k++) {
        int gy = y0 + rbase + k;
        bool yin = (gy >= 2) && (gy < IMG_H - 2);
        float4 v;
        v.x = (yin && gxb + 0 >= 2 && gxb + 0 < IMG_W - 2) ? 0.5f * acc[k * PX + 0] : 0.0f;
        v.y = (yin && gxb + 1 >= 2 && gxb + 1 < IMG_W - 2) ? 0.5f * acc[k * PX + 1] : 0.0f;
        v.z = (yin && gxb + 2 >= 2 && gxb + 2 < IMG_W - 2) ? 0.5f * acc[k * PX + 2] : 0.0f;
        v.w = (yin && gxb + 3 >= 2 && gxb + 3 < IMG_W - 2) ? 0.5f * acc[k * PX + 3] : 0.0f;
        *reinterpret_cast<float4*>(om + gy * IMG_W + gxb) = v;
    }
}

extern "C" void kernel_launch(void* const* d_in, const int* in_sizes, int n_in,
                              void* d_out, int out_size) {
    const float* in = (const float*)d_in[0];
    float* out = (float*)d_out;
    dim3 block(TX, TYB, 1);
    dim3 grid(IMG_W / BW, IMG_H / BH, 96);   // 8 x 4 x 96 = 3072 blocks
    soft_hist_kernel<<<grid, block>>>(in, out);
}

// round 14
// speedup vs baseline: 1.0440x; 1.0440x over previous
#include <cuda_runtime.h>
#include <cuda_bf16.h>

// Soft local histogram, R=5, bandwidth=0.5.
// Input/output: (4, 8, 3, 256, 256) fp32 -> 96 images of 256x256.
// out[y,x] = sum_{di,dj in [-2,2]} max(0, 1 - 2*|x[y+di,x+dj] - x[y,x]|)
// for y,x in [2, 254); zero on the 2-pixel border.
//
// Packed-f32x2 taps (Blackwell FFMA2, PTX-only — ptxas never auto-fuses):
//   d2   = fma.rn.f32x2(a_pair, {2,2}, nc2_pair)     // 2 taps
//   w_lo = __saturatef(fma(|d_lo|, -1, 1))           // scalar per component
//   w_hi = __saturatef(fma(|d_hi|, -1, 1))
//   acc2 = fma.rn.f32x2({w_lo,w_hi}, {2,2}, acc2)    // 2 taps
// 4 issues per 2 taps vs 6 scalar. Centers computed naturally:
// fma(c,2,-2c) == 0 exactly -> w == 1 exactly; acc starts at 0.
// R13 bug fixed: P[6]=(a6,a7) loads from scol0+4 (was scol0+6 -> (a8,a9)).

#define IMG_H 256
#define IMG_W 256
#define TX 8            // threads in x; each covers PX=4 pixels -> 32 wide
#define TYB 32
#define PX 4
#define PY 2
#define BW 32
#define BH (TYB * PY)   // 64 output rows per block
#define TILE_H (BH + 4) // 68
#define TILE_W 56
#define NF4 12
#define NLOAD (TILE_H * NF4)   // 816

typedef unsigned long long u64;

__device__ __forceinline__ u64 ffma2(u64 a, u64 b, u64 c) {
    u64 d;
    asm("fma.rn.f32x2 %0, %1, %2, %3;" : "=l"(d) : "l"(a), "l"(b), "l"(c));
    return d;
}
__device__ __forceinline__ u64 fmul2(u64 a, u64 b) {
    u64 d;
    asm("mul.rn.f32x2 %0, %1, %2;" : "=l"(d) : "l"(a), "l"(b));
    return d;
}
__device__ __forceinline__ u64 pack2(float lo, float hi) {
    u64 r;
    asm("mov.b64 %0, {%1, %2};" : "=l"(r) : "f"(lo), "f"(hi));
    return r;
}
__device__ __forceinline__ void unpack2(u64 v, float& lo, float& hi) {
    asm("mov.b64 {%0, %1}, %2;" : "=f"(lo), "=f"(hi) : "l"(v));
}

#define TWO2  0x4000000040000000ull   // {2.0f, 2.0f}
#define NTWO2 0xC0000000C0000000ull   // {-2.0f, -2.0f}

__global__ __launch_bounds__(TX * TYB, 6) void soft_hist_kernel(
    const float* __restrict__ in, float* __restrict__ out)
{
    __shared__ float tile[TILE_H][TILE_W];

    const int img = blockIdx.z;
    const float* im = in + (size_t)img * IMG_H * IMG_W;
    float* om = out + (size_t)img * IMG_H * IMG_W;

    const int x0 = blockIdx.x * BW;
    const int y0 = blockIdx.y * BH;
    const int tx = threadIdx.x;
    const int ty = threadIdx.y;
    const int tid = ty * TX + tx;

    // 48-float aligned load window from base_x; smem col s = g - base_x + 4.
    // Clamped rows/cols only feed outputs in the forced-zero border.
    int base_x = x0 - 8;
    if (base_x < 0) base_x = 0;
    if (base_x > IMG_W - 48) base_x = IMG_W - 48;   // 208

    for (int idx = tid; idx < NLOAD; idx += TX * TYB) {
        int ly = idx / NF4;
        int lf = idx - ly * NF4;
        int gy = min(max(y0 + ly - 2, 0), IMG_H - 1);
        float4 v = *reinterpret_cast<const float4*>(im + gy * IMG_W + base_x + lf * 4);
        *reinterpret_cast<float4*>(&tile[ly][4 + lf * 4]) = v;
    }
    __syncthreads();

    // Thread outputs: cols gxb + p (p=0..3), rows y0 + ty*PY + k (k=0..1).
    // scol0 4-aligned, scol0-2 and scol0+4 2-aligned: b64 loads all legal.
    const int scol0 = (x0 + PX * tx) - base_x + 4;
    const int rbase = ty * PY;

    // Centers: LDS.128 -> two aligned pairs -> nc2 pairs via mul.f32x2.
    u64 nc2p[PY][2];   // [k][h]: h=0 -> (-2c_p0, -2c_p1), h=1 -> (-2c_p2, -2c_p3)
    u64 acc2[PY][2];   // packed 2*sum accumulators (center included naturally)
    #pragma unroll
    for (int k = 0; k < PY; k++) {
        ulonglong2 c = *reinterpret_cast<const ulonglong2*>(&tile[rbase + k + 2][scol0]);
        nc2p[k][0] = fmul2(c.x, NTWO2);
        nc2p[k][1] = fmul2(c.y, NTWO2);
        acc2[k][0] = 0ull;
        acc2[k][1] = 0ull;
    }

    // Slide over PY+4 tap rows. Row window a[0..7], a[i] at col scol0-2+i.
    // Packed pairs: P[i] = (a[i], a[i+1]).  Pair h (p=2h,2h+1), tap j uses
    // P[j + 2h].  Even P from direct b64/b128 loads, odd P packed.
    #pragma unroll
    for (int ry = 0; ry < PY + 4; ry++) {
        const float* row = &tile[rbase + ry][0];
        u64 P[7];
        P[0] = *reinterpret_cast<const u64*>(row + scol0 - 2);          // (a0,a1)
        {
            ulonglong2 md = *reinterpret_cast<const ulonglong2*>(row + scol0);
            P[2] = md.x;                                                // (a2,a3)
            P[4] = md.y;                                                // (a4,a5)
        }
        P[6] = *reinterpret_cast<const u64*>(row + scol0 + 4);          // (a6,a7)
        {
            float a0, a1, a2, a3, a4, a5, a6, a7;
            unpack2(P[0], a0, a1);
            unpack2(P[2], a2, a3);
            unpack2(P[4], a4, a5);
            unpack2(P[6], a6, a7);
            P[1] = pack2(a1, a2);
            P[3] = pack2(a3, a4);
            P[5] = pack2(a5, a6);
        }
        #pragma unroll
        for (int k = 0; k < PY; k++) {
            if (ry >= k && ry <= k + 4) {
                #pragma unroll
                for (int h = 0; h < 2; h++) {
                    #pragma unroll
                    for (int j = 0; j < 5; j++) {
                        u64 d2 = ffma2(P[j + 2 * h], TWO2, nc2p[k][h]);   // 2 taps
                        float dlo, dhi;
                        unpack2(d2, dlo, dhi);
                        float wlo = __saturatef(fmaf(fabsf(dlo), -1.0f, 1.0f));
                        float whi = __saturatef(fmaf(fabsf(dhi), -1.0f, 1.0f));
                        acc2[k][h] = ffma2(pack2(wlo, whi), TWO2, acc2[k][h]);
                    }
                }
            }
        }
    }

    // Epilogue: border select + 0.5x scale, one STG.128 per output row.
    const int gxb = x0 + PX * tx;
    #pragma unroll
    for (int k = 0; k < PY; k++) {
        int gy = y0 + rbase + k;
        bool yin = (gy >= 2) && (gy < IMG_H - 2);
        float s0, s1, s2, s3;
        unpack2(acc2[k][0], s0, s1);
        unpack2(acc2[k][1], s2, s3);
        float4 v;
        v.x = (yin && gxb + 0 >= 2 && gxb + 0 < IMG_W - 2) ? 0.5f * s0 : 0.0f;
        v.y = (yin && gxb + 1 >= 2 && gxb + 1 < IMG_W - 2) ? 0.5f * s1 : 0.0f;
        v.z = (yin && gxb + 2 >= 2 && gxb + 2 < IMG_W - 2) ? 0.5f * s2 : 0.0f;
        v.w = (yin && gxb + 3 >= 2 && gxb + 3 < IMG_W - 2) ? 0.5f * s3 : 0.0f;
        *reinterpret_cast<float4*>(om + gy * IMG_W + gxb) = v;
    }
}

extern "C" void kernel_launch(void* const* d_in, const int* in_sizes, int n_in,
                              void* d_out, int out_size) {
    const float* in = (const float*)d_in[0];
    float* out = (float*)d_out;
    dim3 block(TX, TYB, 1);
    dim3 grid(IMG_W / BW, IMG_H / BH, 96);   // 8 x 4 x 96 = 3072 blocks
    soft_hist_kernel<<<grid, block>>>(in, out);
}